// round 1
// baseline (speedup 1.0000x reference)
#include <cuda_runtime.h>

// Problem constants
#define BATCH   2
#define S_LEN   4096
#define DMODEL  512
#define NHEAD   8
#define DHEAD   64
#define WNBR    32
#define M_TOT   (BATCH * S_LEN)      // 8192
#define PITCH   516                  // 516 mod 32 == 4 -> conflict-free float4 phases

// Scratch (allocation-free rule: device globals)
__device__ float g_q[M_TOT * DMODEL];
__device__ float g_k[M_TOT * DMODEL];
__device__ float g_v[M_TOT * DMODEL];
__device__ float g_a[M_TOT * DMODEL];

// ---------------------------------------------------------------------------
// C[M,N] = A[M,K] * B[N,K]^T   (row-major A, row-major B of shape N x K)
// BM=128, BN=64, BK=16, 256 threads, 8x4 outputs per thread.
// ---------------------------------------------------------------------------
__global__ __launch_bounds__(256)
void gemm_atb(const float* __restrict__ A,
              const float* __restrict__ Bw,
              float* __restrict__ C,
              int M, int N, int K)
{
    __shared__ float As[16][128];
    __shared__ float Bs[16][64];

    const int t  = threadIdx.x;
    const int m0 = blockIdx.y * 128;
    const int n0 = blockIdx.x * 64;
    const int tx = t & 15;     // 0..15 -> 4 cols each
    const int ty = t >> 4;     // 0..15 -> 8 rows each

    float acc[8][4];
#pragma unroll
    for (int i = 0; i < 8; i++)
#pragma unroll
        for (int j = 0; j < 4; j++) acc[i][j] = 0.0f;

    for (int k0 = 0; k0 < K; k0 += 16) {
        // Load A tile (128 x 16): 2 float4 per thread, store transposed
#pragma unroll
        for (int i = 0; i < 2; i++) {
            int e   = t + i * 256;          // 0..511
            int row = e >> 2;               // 0..127
            int c4  = (e & 3) * 4;          // 0,4,8,12
            float4 va = *(const float4*)(A + (m0 + row) * K + k0 + c4);
            As[c4 + 0][row] = va.x;
            As[c4 + 1][row] = va.y;
            As[c4 + 2][row] = va.z;
            As[c4 + 3][row] = va.w;
        }
        // Load B tile (64 x 16): 1 float4 per thread, store transposed
        {
            int row = t >> 2;               // 0..63
            int c4  = (t & 3) * 4;
            float4 vb = *(const float4*)(Bw + (n0 + row) * K + k0 + c4);
            Bs[c4 + 0][row] = vb.x;
            Bs[c4 + 1][row] = vb.y;
            Bs[c4 + 2][row] = vb.z;
            Bs[c4 + 3][row] = vb.w;
        }
        __syncthreads();

#pragma unroll
        for (int kk = 0; kk < 16; kk++) {
            float a[8], b[4];
#pragma unroll
            for (int i = 0; i < 8; i++) a[i] = As[kk][ty * 8 + i];
#pragma unroll
            for (int j = 0; j < 4; j++) b[j] = Bs[kk][tx * 4 + j];
#pragma unroll
            for (int i = 0; i < 8; i++)
#pragma unroll
                for (int j = 0; j < 4; j++)
                    acc[i][j] += a[i] * b[j];
        }
        __syncthreads();
    }

#pragma unroll
    for (int i = 0; i < 8; i++) {
        float4 v4 = make_float4(acc[i][0], acc[i][1], acc[i][2], acc[i][3]);
        *(float4*)(C + (m0 + ty * 8 + i) * N + n0 + tx * 4) = v4;
    }
}

// ---------------------------------------------------------------------------
// Neighbor attention. One CTA per (b, s); 8 warps = 8 heads.
// The 32 neighbor K rows (full 512-float rows, all heads) are staged in smem
// once and reused by all 8 heads, then the buffer is reused for V rows.
// Lane w owns neighbor w: serial dot over d (conflict-free float4 LDS via
// PITCH=516), warp-shuffle softmax, then broadcast p_w for the PV product.
// ---------------------------------------------------------------------------
__global__ __launch_bounds__(256)
void attn_kernel(const float* __restrict__ q,
                 const float* __restrict__ k,
                 const float* __restrict__ v,
                 const int*   __restrict__ nidx,
                 float* __restrict__ out)
{
    extern __shared__ float sm[];           // WNBR * PITCH floats
    __shared__ int   sj[WNBR];
    __shared__ float sq[DMODEL];

    const int bs   = blockIdx.x;            // b*S + s
    const int s    = bs & (S_LEN - 1);
    const int b    = bs >> 12;
    const int t    = threadIdx.x;
    const int h    = t >> 5;                // warp == head
    const int lane = t & 31;

    if (t < WNBR) sj[t] = nidx[s * WNBR + t];
    if (t < DMODEL / 4) {
        float4 qv = *(const float4*)(q + bs * DMODEL + t * 4);
        *(float4*)(sq + t * 4) = qv;
    }
    __syncthreads();

    // Phase 1: stage K neighbor rows
#pragma unroll
    for (int i = 0; i < 16; i++) {
        int e  = t + i * 256;               // 0..4095 float4 slots
        int w  = e >> 7;                    // neighbor row
        int c4 = (e & 127) * 4;
        float4 val = *(const float4*)(k + (b * S_LEN + sj[w]) * DMODEL + c4);
        *(float4*)(sm + w * PITCH + c4) = val;
    }
    __syncthreads();

    // Scores: lane handles neighbor `lane`
    float acc = 0.0f;
    {
        const float* kr = sm + lane * PITCH + h * DHEAD;
        const float* qr = sq + h * DHEAD;
#pragma unroll
        for (int d = 0; d < DHEAD; d += 4) {
            float4 kv = *(const float4*)(kr + d);
            float4 qv = *(const float4*)(qr + d);
            acc += qv.x * kv.x + qv.y * kv.y + qv.z * kv.z + qv.w * kv.w;
        }
    }
    float score = acc * 0.125f;             // 1/sqrt(64)

    // Warp softmax over the 32 lanes
    float m = score;
#pragma unroll
    for (int o = 16; o; o >>= 1) m = fmaxf(m, __shfl_xor_sync(0xffffffffu, m, o));
    float e = expf(score - m);
    float ssum = e;
#pragma unroll
    for (int o = 16; o; o >>= 1) ssum += __shfl_xor_sync(0xffffffffu, ssum, o);
    float p = e / ssum;

    // Phase 2: stage V neighbor rows (reuse buffer)
    __syncthreads();
#pragma unroll
    for (int i = 0; i < 16; i++) {
        int e2 = t + i * 256;
        int w  = e2 >> 7;
        int c4 = (e2 & 127) * 4;
        float4 val = *(const float4*)(v + (b * S_LEN + sj[w]) * DMODEL + c4);
        *(float4*)(sm + w * PITCH + c4) = val;
    }
    __syncthreads();

    // out[d] = sum_w p_w * v_w[d]; lane handles d=lane and d=lane+32
    float o0 = 0.0f, o1 = 0.0f;
#pragma unroll
    for (int w = 0; w < WNBR; w++) {
        float pw = __shfl_sync(0xffffffffu, p, w);
        o0 += pw * sm[w * PITCH + h * DHEAD + lane];
        o1 += pw * sm[w * PITCH + h * DHEAD + 32 + lane];
    }
    out[bs * DMODEL + h * DHEAD + lane]      = o0;
    out[bs * DMODEL + h * DHEAD + 32 + lane] = o1;
}

// ---------------------------------------------------------------------------
extern "C" void kernel_launch(void* const* d_in, const int* in_sizes, int n_in,
                              void* d_out, int out_size)
{
    const float* x    = (const float*)d_in[0];
    const float* Wq   = (const float*)d_in[1];
    const float* Wk   = (const float*)d_in[2];
    const float* Wv   = (const float*)d_in[3];
    const float* Wo   = (const float*)d_in[4];
    const int*   nidx = (const int*)  d_in[5];
    float*       out  = (float*)d_out;

    float *q, *k, *v, *a;
    cudaGetSymbolAddress((void**)&q, g_q);
    cudaGetSymbolAddress((void**)&k, g_k);
    cudaGetSymbolAddress((void**)&v, g_v);
    cudaGetSymbolAddress((void**)&a, g_a);

    static int smem_set = 0;
    if (!smem_set) {
        cudaFuncSetAttribute(attn_kernel,
                             cudaFuncAttributeMaxDynamicSharedMemorySize,
                             WNBR * PITCH * (int)sizeof(float));
        smem_set = 1;
    }

    dim3 grid(DMODEL / 64, M_TOT / 128);   // (8, 64)
    gemm_atb<<<grid, 256>>>(x, Wq, q, M_TOT, DMODEL, DMODEL);
    gemm_atb<<<grid, 256>>>(x, Wk, k, M_TOT, DMODEL, DMODEL);
    gemm_atb<<<grid, 256>>>(x, Wv, v, M_TOT, DMODEL, DMODEL);

    attn_kernel<<<M_TOT, 256, WNBR * PITCH * (int)sizeof(float)>>>(q, k, v, nidx, a);

    gemm_atb<<<grid, 256>>>(a, Wo, out, M_TOT, DMODEL, DMODEL);
}

// round 3
// speedup vs baseline: 1.8120x; 1.8120x over previous
#include <cuda_runtime.h>
#include <cuda_bf16.h>
#include <cstdint>

// Problem constants
#define BATCH   2
#define S_LEN   4096
#define DMODEL  512
#define NHEAD   8
#define DHEAD   64
#define WNBR    32
#define M_TOT   (BATCH * S_LEN)      // 8192
#define PITCH   516

// ---------------------------------------------------------------------------
// PTX helpers — base sm_103 only (NO tcgen05 / no "a"-suffix features)
// ---------------------------------------------------------------------------
__device__ __forceinline__ uint32_t smem_to_u32(const void* p) {
    uint32_t a;
    asm("{ .reg .u64 t; cvta.to.shared.u64 t, %1; cvt.u32.u64 %0, t; }" : "=r"(a) : "l"(p));
    return a;
}

__device__ __forceinline__ void ldsm_x4(uint32_t* r, uint32_t addr) {
    asm volatile("ldmatrix.sync.aligned.m8n8.x4.shared.b16 {%0,%1,%2,%3}, [%4];"
                 : "=r"(r[0]), "=r"(r[1]), "=r"(r[2]), "=r"(r[3]) : "r"(addr));
}

__device__ __forceinline__ void mma_bf16_16816(float* d,
                                               const uint32_t* a,
                                               uint32_t b0, uint32_t b1) {
    asm volatile(
        "mma.sync.aligned.m16n8k16.row.col.f32.bf16.bf16.f32 "
        "{%0,%1,%2,%3}, {%4,%5,%6,%7}, {%8,%9}, {%0,%1,%2,%3};"
        : "+f"(d[0]), "+f"(d[1]), "+f"(d[2]), "+f"(d[3])
        : "r"(a[0]), "r"(a[1]), "r"(a[2]), "r"(a[3]), "r"(b0), "r"(b1));
}

#define CP_ASYNC16(sa, gp) \
    asm volatile("cp.async.cg.shared.global [%0], [%1], 16;" :: "r"(sa), "l"(gp))
#define CP_COMMIT() asm volatile("cp.async.commit_group;")
#define CP_WAIT1()  asm volatile("cp.async.wait_group 1;")
#define CP_WAIT0()  asm volatile("cp.async.wait_group 0;")

// ---------------------------------------------------------------------------
// Scratch (allocation-free rule: device globals)
// ---------------------------------------------------------------------------
__device__ float g_q[M_TOT * DMODEL];
__device__ float g_k[M_TOT * DMODEL];
__device__ float g_v[M_TOT * DMODEL];
__device__ float g_a[M_TOT * DMODEL];
__device__ __align__(256) __nv_bfloat16 g_ahi[M_TOT * DMODEL];
__device__ __align__(256) __nv_bfloat16 g_alo[M_TOT * DMODEL];
__device__ __align__(256) __nv_bfloat16 g_whi[4][DMODEL * DMODEL];
__device__ __align__(256) __nv_bfloat16 g_wlo[4][DMODEL * DMODEL];

// ---------------------------------------------------------------------------
// fp32 -> (bf16 hi, bf16 lo) split
// ---------------------------------------------------------------------------
__global__ __launch_bounds__(256)
void split_kernel(const float* __restrict__ in,
                  __nv_bfloat16* __restrict__ hi,
                  __nv_bfloat16* __restrict__ lo, int n4)
{
    int i = blockIdx.x * blockDim.x + threadIdx.x;
    if (i >= n4) return;
    float4 x = ((const float4*)in)[i];
    __nv_bfloat16 h0 = __float2bfloat16(x.x);
    __nv_bfloat16 h1 = __float2bfloat16(x.y);
    __nv_bfloat16 h2 = __float2bfloat16(x.z);
    __nv_bfloat16 h3 = __float2bfloat16(x.w);
    ((__nv_bfloat162*)hi)[i * 2 + 0] = __nv_bfloat162(h0, h1);
    ((__nv_bfloat162*)hi)[i * 2 + 1] = __nv_bfloat162(h2, h3);
    ((__nv_bfloat162*)lo)[i * 2 + 0] =
        __nv_bfloat162(__float2bfloat16(x.x - __bfloat162float(h0)),
                       __float2bfloat16(x.y - __bfloat162float(h1)));
    ((__nv_bfloat162*)lo)[i * 2 + 1] =
        __nv_bfloat162(__float2bfloat16(x.z - __bfloat162float(h2)),
                       __float2bfloat16(x.w - __bfloat162float(h3)));
}

// ---------------------------------------------------------------------------
// HMMA bf16x3 GEMM: C[M,512] = A[M,512] * B[512,512]^T (both row-major, K-major)
// CTA 128x128, BK=32, 256 threads, warp grid 2(M) x 4(N), warp tile 64x32.
// Smem rows padded to 40 bf16 (80B) -> conflict-free ldmatrix (5 coprime 8).
// cp.async double buffer over 16 K-chunks.
// ---------------------------------------------------------------------------
#define ASTRIDE 40
#define TILE_B  (128 * ASTRIDE * 2)   // 10240 bytes per 128x32 tile
#define BUF_B   (4 * TILE_B)          // Ahi|Alo|Bhi|Blo = 40960
#define GEMM_SMEM (2 * BUF_B)         // 81920

__global__ __launch_bounds__(256)
void gemm_hmma_x3(const __nv_bfloat16* __restrict__ Ahi, const __nv_bfloat16* __restrict__ Alo,
                  const __nv_bfloat16* __restrict__ Bhi, const __nv_bfloat16* __restrict__ Blo,
                  float* __restrict__ C)
{
    extern __shared__ char smc[];
    const uint32_t sbase = smem_to_u32(smc);
    const int t = threadIdx.x, lane = t & 31, wid = t >> 5;
    const int wm = wid & 1;           // 0..1 -> 64-row slab
    const int wn = wid >> 1;          // 0..3 -> 32-col slab
    const int m0 = blockIdx.y * 128;
    const int n0 = blockIdx.x * 128;

    float acc[4][4][4];
#pragma unroll
    for (int mi = 0; mi < 4; mi++)
#pragma unroll
        for (int ni = 0; ni < 4; ni++)
#pragma unroll
            for (int j = 0; j < 4; j++) acc[mi][ni][j] = 0.0f;

    // per-thread cp.async coords (2 chunks of 16B per tile per thread)
    const int e0row = t >> 2,           e0c = (t & 3) * 8;
    const int e1row = (t + 256) >> 2,   e1c = ((t + 256) & 3) * 8;
    const uint32_t so0 = (uint32_t)(e0row * ASTRIDE + e0c) * 2;
    const uint32_t so1 = (uint32_t)(e1row * ASTRIDE + e1c) * 2;

#define LOAD_CHUNK(kc, buf) do { \
    uint32_t bb = sbase + (uint32_t)(buf) * BUF_B; \
    size_t ga0 = (size_t)(m0 + e0row) * DMODEL + (kc) + e0c; \
    size_t ga1 = (size_t)(m0 + e1row) * DMODEL + (kc) + e1c; \
    size_t gb0 = (size_t)(n0 + e0row) * DMODEL + (kc) + e0c; \
    size_t gb1 = (size_t)(n0 + e1row) * DMODEL + (kc) + e1c; \
    CP_ASYNC16(bb + so0,              Ahi + ga0); \
    CP_ASYNC16(bb + so1,              Ahi + ga1); \
    CP_ASYNC16(bb + TILE_B + so0,     Alo + ga0); \
    CP_ASYNC16(bb + TILE_B + so1,     Alo + ga1); \
    CP_ASYNC16(bb + 2 * TILE_B + so0, Bhi + gb0); \
    CP_ASYNC16(bb + 2 * TILE_B + so1, Bhi + gb1); \
    CP_ASYNC16(bb + 3 * TILE_B + so0, Blo + gb0); \
    CP_ASYNC16(bb + 3 * TILE_B + so1, Blo + gb1); \
} while (0)

    LOAD_CHUNK(0, 0);
    CP_COMMIT();

    const int lrow = lane & 15;
    const int lcol = lane >> 4;

    for (int c = 0; c < 16; c++) {
        if (c < 15) LOAD_CHUNK((c + 1) * 32, (c + 1) & 1);
        CP_COMMIT();
        CP_WAIT1();
        __syncthreads();

        const uint32_t ab = sbase + (uint32_t)(c & 1) * BUF_B;
#pragma unroll
        for (int ks = 0; ks < 2; ks++) {
            uint32_t ah[4][4], al[4][4], bh[2][4], bl[2][4];
            const int kcol = ks * 2 + lcol;          // 16B-chunk index 0..3
#pragma unroll
            for (int mi = 0; mi < 4; mi++) {
                uint32_t ad = ab + (uint32_t)(((wm * 64 + mi * 16 + lrow) * ASTRIDE) + kcol * 8) * 2;
                ldsm_x4(ah[mi], ad);
                ldsm_x4(al[mi], ad + TILE_B);
            }
#pragma unroll
            for (int nb = 0; nb < 2; nb++) {
                uint32_t bd = ab + 2 * TILE_B +
                              (uint32_t)(((wn * 32 + nb * 16 + lrow) * ASTRIDE) + kcol * 8) * 2;
                ldsm_x4(bh[nb], bd);
                ldsm_x4(bl[nb], bd + TILE_B);
            }
#pragma unroll
            for (int mi = 0; mi < 4; mi++)
#pragma unroll
                for (int ni = 0; ni < 4; ni++) {
                    const int nb = ni >> 1, nl = ni & 1;
                    mma_bf16_16816(acc[mi][ni], ah[mi], bh[nb][nl], bh[nb][nl + 2]);
                    mma_bf16_16816(acc[mi][ni], ah[mi], bl[nb][nl], bl[nb][nl + 2]);
                    mma_bf16_16816(acc[mi][ni], al[mi], bh[nb][nl], bh[nb][nl + 2]);
                }
        }
        __syncthreads();
    }
    CP_WAIT0();

    // Epilogue: write fp32 accumulators
#pragma unroll
    for (int mi = 0; mi < 4; mi++) {
        const int r0 = m0 + wm * 64 + mi * 16 + (lane >> 2);
#pragma unroll
        for (int ni = 0; ni < 4; ni++) {
            const int cc = n0 + wn * 32 + ni * 8 + (lane & 3) * 2;
            *(float2*)(C + (size_t)r0 * DMODEL + cc)       = make_float2(acc[mi][ni][0], acc[mi][ni][1]);
            *(float2*)(C + (size_t)(r0 + 8) * DMODEL + cc) = make_float2(acc[mi][ni][2], acc[mi][ni][3]);
        }
    }
#undef LOAD_CHUNK
}

// ---------------------------------------------------------------------------
// Neighbor attention (unchanged). One CTA per (b,s); 8 warps = 8 heads.
// ---------------------------------------------------------------------------
__global__ __launch_bounds__(256)
void attn_kernel(const float* __restrict__ q,
                 const float* __restrict__ k,
                 const float* __restrict__ v,
                 const int*   __restrict__ nidx,
                 float* __restrict__ out)
{
    extern __shared__ float sm[];
    __shared__ int   sj[WNBR];
    __shared__ float sq[DMODEL];

    const int bs   = blockIdx.x;
    const int s    = bs & (S_LEN - 1);
    const int b    = bs >> 12;
    const int t    = threadIdx.x;
    const int h    = t >> 5;
    const int lane = t & 31;

    if (t < WNBR) sj[t] = nidx[s * WNBR + t];
    if (t < DMODEL / 4) {
        float4 qv = *(const float4*)(q + bs * DMODEL + t * 4);
        *(float4*)(sq + t * 4) = qv;
    }
    __syncthreads();

#pragma unroll
    for (int i = 0; i < 16; i++) {
        int e  = t + i * 256;
        int w  = e >> 7;
        int c4 = (e & 127) * 4;
        float4 val = *(const float4*)(k + (b * S_LEN + sj[w]) * DMODEL + c4);
        *(float4*)(sm + w * PITCH + c4) = val;
    }
    __syncthreads();

    float acc = 0.0f;
    {
        const float* kr = sm + lane * PITCH + h * DHEAD;
        const float* qr = sq + h * DHEAD;
#pragma unroll
        for (int d = 0; d < DHEAD; d += 4) {
            float4 kv = *(const float4*)(kr + d);
            float4 qv = *(const float4*)(qr + d);
            acc += qv.x * kv.x + qv.y * kv.y + qv.z * kv.z + qv.w * kv.w;
        }
    }
    float score = acc * 0.125f;

    float m = score;
#pragma unroll
    for (int o = 16; o; o >>= 1) m = fmaxf(m, __shfl_xor_sync(0xffffffffu, m, o));
    float e = expf(score - m);
    float ssum = e;
#pragma unroll
    for (int o = 16; o; o >>= 1) ssum += __shfl_xor_sync(0xffffffffu, ssum, o);
    float p = e / ssum;

    __syncthreads();
#pragma unroll
    for (int i = 0; i < 16; i++) {
        int e2 = t + i * 256;
        int w  = e2 >> 7;
        int c4 = (e2 & 127) * 4;
        float4 val = *(const float4*)(v + (b * S_LEN + sj[w]) * DMODEL + c4);
        *(float4*)(sm + w * PITCH + c4) = val;
    }
    __syncthreads();

    float o0 = 0.0f, o1 = 0.0f;
#pragma unroll
    for (int w = 0; w < WNBR; w++) {
        float pw = __shfl_sync(0xffffffffu, p, w);
        o0 += pw * sm[w * PITCH + h * DHEAD + lane];
        o1 += pw * sm[w * PITCH + h * DHEAD + 32 + lane];
    }
    out[bs * DMODEL + h * DHEAD + lane]      = o0;
    out[bs * DMODEL + h * DHEAD + 32 + lane] = o1;
}

// ---------------------------------------------------------------------------
extern "C" void kernel_launch(void* const* d_in, const int* in_sizes, int n_in,
                              void* d_out, int out_size)
{
    const float* x    = (const float*)d_in[0];
    const float* Wq   = (const float*)d_in[1];
    const float* Wk   = (const float*)d_in[2];
    const float* Wv   = (const float*)d_in[3];
    const float* Wo   = (const float*)d_in[4];
    const int*   nidx = (const int*)  d_in[5];
    float*       out  = (float*)d_out;

    float *q, *k, *v, *a;
    __nv_bfloat16 *ahi, *alo, *whi, *wlo;
    cudaGetSymbolAddress((void**)&q,   g_q);
    cudaGetSymbolAddress((void**)&k,   g_k);
    cudaGetSymbolAddress((void**)&v,   g_v);
    cudaGetSymbolAddress((void**)&a,   g_a);
    cudaGetSymbolAddress((void**)&ahi, g_ahi);
    cudaGetSymbolAddress((void**)&alo, g_alo);
    cudaGetSymbolAddress((void**)&whi, g_whi);
    cudaGetSymbolAddress((void**)&wlo, g_wlo);

    static int attr_set = 0;
    if (!attr_set) {
        cudaFuncSetAttribute(attn_kernel, cudaFuncAttributeMaxDynamicSharedMemorySize,
                             WNBR * PITCH * (int)sizeof(float));
        cudaFuncSetAttribute(gemm_hmma_x3, cudaFuncAttributeMaxDynamicSharedMemorySize,
                             GEMM_SMEM);
        attr_set = 1;
    }

    const int NW  = DMODEL * DMODEL;          // 262144
    const int nx4 = M_TOT * DMODEL / 4;       // 1048576
    const int nw4 = NW / 4;                   // 65536

    split_kernel<<<(nx4 + 255) / 256, 256>>>(x,  ahi, alo, nx4);
    split_kernel<<<(nw4 + 255) / 256, 256>>>(Wq, whi + 0 * NW, wlo + 0 * NW, nw4);
    split_kernel<<<(nw4 + 255) / 256, 256>>>(Wk, whi + 1 * NW, wlo + 1 * NW, nw4);
    split_kernel<<<(nw4 + 255) / 256, 256>>>(Wv, whi + 2 * NW, wlo + 2 * NW, nw4);
    split_kernel<<<(nw4 + 255) / 256, 256>>>(Wo, whi + 3 * NW, wlo + 3 * NW, nw4);

    dim3 ggrid(DMODEL / 128, M_TOT / 128);    // (4, 64)
    gemm_hmma_x3<<<ggrid, 256, GEMM_SMEM>>>(ahi, alo, whi + 0 * NW, wlo + 0 * NW, q);
    gemm_hmma_x3<<<ggrid, 256, GEMM_SMEM>>>(ahi, alo, whi + 1 * NW, wlo + 1 * NW, k);
    gemm_hmma_x3<<<ggrid, 256, GEMM_SMEM>>>(ahi, alo, whi + 2 * NW, wlo + 2 * NW, v);

    attn_kernel<<<M_TOT, 256, WNBR * PITCH * (int)sizeof(float)>>>(q, k, v, nidx, a);

    split_kernel<<<(nx4 + 255) / 256, 256>>>(a, ahi, alo, nx4);
    gemm_hmma_x3<<<ggrid, 256, GEMM_SMEM>>>(ahi, alo, whi + 3 * NW, wlo + 3 * NW, out);
}

// round 4
// speedup vs baseline: 2.6651x; 1.4709x over previous
#include <cuda_runtime.h>
#include <cuda_bf16.h>
#include <cuda_fp16.h>
#include <cstdint>

// Problem constants
#define BATCH   2
#define S_LEN   4096
#define DMODEL  512
#define NHEAD   8
#define DHEAD   64
#define WNBR    32
#define M_TOT   (BATCH * S_LEN)      // 8192

// ---------------------------------------------------------------------------
// PTX helpers — base sm_103 only (NO tcgen05)
// ---------------------------------------------------------------------------
__device__ __forceinline__ uint32_t smem_to_u32(const void* p) {
    uint32_t a;
    asm("{ .reg .u64 t; cvta.to.shared.u64 t, %1; cvt.u32.u64 %0, t; }" : "=r"(a) : "l"(p));
    return a;
}
__device__ __forceinline__ void ldsm_x4(uint32_t* r, uint32_t addr) {
    asm volatile("ldmatrix.sync.aligned.m8n8.x4.shared.b16 {%0,%1,%2,%3}, [%4];"
                 : "=r"(r[0]), "=r"(r[1]), "=r"(r[2]), "=r"(r[3]) : "r"(addr));
}
__device__ __forceinline__ void mma_bf16_16816(float* d, const uint32_t* a,
                                               uint32_t b0, uint32_t b1) {
    asm volatile(
        "mma.sync.aligned.m16n8k16.row.col.f32.bf16.bf16.f32 "
        "{%0,%1,%2,%3}, {%4,%5,%6,%7}, {%8,%9}, {%0,%1,%2,%3};"
        : "+f"(d[0]), "+f"(d[1]), "+f"(d[2]), "+f"(d[3])
        : "r"(a[0]), "r"(a[1]), "r"(a[2]), "r"(a[3]), "r"(b0), "r"(b1));
}
#define CP_ASYNC16(sa, gp) \
    asm volatile("cp.async.cg.shared.global [%0], [%1], 16;" :: "r"(sa), "l"(gp))
#define CP_COMMIT() asm volatile("cp.async.commit_group;")
#define CP_WAIT1()  asm volatile("cp.async.wait_group 1;")
#define CP_WAIT0()  asm volatile("cp.async.wait_group 0;")

// ---------------------------------------------------------------------------
// Scratch (allocation-free rule: device globals)
// ---------------------------------------------------------------------------
__device__ float g_q[M_TOT * DMODEL];                     // Q fp32
__device__ __align__(256) __half g_k16[M_TOT * DMODEL];   // K fp16
__device__ __align__(256) __half g_v16[M_TOT * DMODEL];   // V fp16
__device__ __align__(256) __nv_bfloat16 g_ahi[M_TOT * DMODEL];
__device__ __align__(256) __nv_bfloat16 g_alo[M_TOT * DMODEL];
// weights: rows 0..511 Wq, 512..1023 Wk, 1024..1535 Wv, 1536..2047 Wo
__device__ __align__(256) __nv_bfloat16 g_whi[4 * DMODEL * DMODEL];
__device__ __align__(256) __nv_bfloat16 g_wlo[4 * DMODEL * DMODEL];

// ---------------------------------------------------------------------------
// fp32 -> (bf16 hi, bf16 lo) split: x activations
// ---------------------------------------------------------------------------
__global__ __launch_bounds__(256)
void split_kernel(const float* __restrict__ in,
                  __nv_bfloat16* __restrict__ hi,
                  __nv_bfloat16* __restrict__ lo, int n4)
{
    int i = blockIdx.x * blockDim.x + threadIdx.x;
    if (i >= n4) return;
    float4 x = ((const float4*)in)[i];
    __nv_bfloat16 h0 = __float2bfloat16(x.x), h1 = __float2bfloat16(x.y);
    __nv_bfloat16 h2 = __float2bfloat16(x.z), h3 = __float2bfloat16(x.w);
    ((__nv_bfloat162*)hi)[i * 2 + 0] = __nv_bfloat162(h0, h1);
    ((__nv_bfloat162*)hi)[i * 2 + 1] = __nv_bfloat162(h2, h3);
    ((__nv_bfloat162*)lo)[i * 2 + 0] =
        __nv_bfloat162(__float2bfloat16(x.x - __bfloat162float(h0)),
                       __float2bfloat16(x.y - __bfloat162float(h1)));
    ((__nv_bfloat162*)lo)[i * 2 + 1] =
        __nv_bfloat162(__float2bfloat16(x.z - __bfloat162float(h2)),
                       __float2bfloat16(x.w - __bfloat162float(h3)));
}

// Fused split of the 4 weight matrices into concatenated hi/lo buffers
__global__ __launch_bounds__(256)
void split4_kernel(const float* __restrict__ w0, const float* __restrict__ w1,
                   const float* __restrict__ w2, const float* __restrict__ w3,
                   __nv_bfloat16* __restrict__ hi, __nv_bfloat16* __restrict__ lo)
{
    int i = blockIdx.x * blockDim.x + threadIdx.x;   // 0 .. 4*65536-1
    int w = i >> 16, l = i & 65535;
    const float* src = (w == 0) ? w0 : (w == 1) ? w1 : (w == 2) ? w2 : w3;
    float4 x = ((const float4*)src)[l];
    __nv_bfloat16 h0 = __float2bfloat16(x.x), h1 = __float2bfloat16(x.y);
    __nv_bfloat16 h2 = __float2bfloat16(x.z), h3 = __float2bfloat16(x.w);
    ((__nv_bfloat162*)hi)[i * 2 + 0] = __nv_bfloat162(h0, h1);
    ((__nv_bfloat162*)hi)[i * 2 + 1] = __nv_bfloat162(h2, h3);
    ((__nv_bfloat162*)lo)[i * 2 + 0] =
        __nv_bfloat162(__float2bfloat16(x.x - __bfloat162float(h0)),
                       __float2bfloat16(x.y - __bfloat162float(h1)));
    ((__nv_bfloat162*)lo)[i * 2 + 1] =
        __nv_bfloat162(__float2bfloat16(x.z - __bfloat162float(h2)),
                       __float2bfloat16(x.w - __bfloat162float(h3)));
}

// ---------------------------------------------------------------------------
// HMMA bf16x3 GEMM core. CTA 128x128, BK=32, 256 threads, warp tile 64x32.
// EPI: 0 = fp32 C ; 1 = QKV (q fp32 / k,v fp16 by n0 block)
// ---------------------------------------------------------------------------
#define ASTRIDE 40
#define TILE_B  (128 * ASTRIDE * 2)
#define BUF_B   (4 * TILE_B)
#define GEMM_SMEM (2 * BUF_B)         // 81920

template <int EPI>
__device__ __forceinline__
void gemm_core(const __nv_bfloat16* __restrict__ Ahi, const __nv_bfloat16* __restrict__ Alo,
               const __nv_bfloat16* __restrict__ Bhi, const __nv_bfloat16* __restrict__ Blo,
               float* __restrict__ C, __half* __restrict__ K16, __half* __restrict__ V16)
{
    extern __shared__ char smc[];
    const uint32_t sbase = smem_to_u32(smc);
    const int t = threadIdx.x, lane = t & 31, wid = t >> 5;
    const int wm = wid & 1, wn = wid >> 1;
    const int m0 = blockIdx.y * 128;
    const int n0 = blockIdx.x * 128;

    float acc[4][4][4];
#pragma unroll
    for (int mi = 0; mi < 4; mi++)
#pragma unroll
        for (int ni = 0; ni < 4; ni++)
#pragma unroll
            for (int j = 0; j < 4; j++) acc[mi][ni][j] = 0.0f;

    const int e0row = t >> 2,         e0c = (t & 3) * 8;
    const int e1row = (t + 256) >> 2, e1c = ((t + 256) & 3) * 8;
    const uint32_t so0 = (uint32_t)(e0row * ASTRIDE + e0c) * 2;
    const uint32_t so1 = (uint32_t)(e1row * ASTRIDE + e1c) * 2;

#define LOAD_CHUNK(kc, buf) do { \
    uint32_t bb = sbase + (uint32_t)(buf) * BUF_B; \
    size_t ga0 = (size_t)(m0 + e0row) * DMODEL + (kc) + e0c; \
    size_t ga1 = (size_t)(m0 + e1row) * DMODEL + (kc) + e1c; \
    size_t gb0 = (size_t)(n0 + e0row) * DMODEL + (kc) + e0c; \
    size_t gb1 = (size_t)(n0 + e1row) * DMODEL + (kc) + e1c; \
    CP_ASYNC16(bb + so0,              Ahi + ga0); \
    CP_ASYNC16(bb + so1,              Ahi + ga1); \
    CP_ASYNC16(bb + TILE_B + so0,     Alo + ga0); \
    CP_ASYNC16(bb + TILE_B + so1,     Alo + ga1); \
    CP_ASYNC16(bb + 2 * TILE_B + so0, Bhi + gb0); \
    CP_ASYNC16(bb + 2 * TILE_B + so1, Bhi + gb1); \
    CP_ASYNC16(bb + 3 * TILE_B + so0, Blo + gb0); \
    CP_ASYNC16(bb + 3 * TILE_B + so1, Blo + gb1); \
} while (0)

    LOAD_CHUNK(0, 0);
    CP_COMMIT();

    const int lrow = lane & 15;
    const int lcol = lane >> 4;

    for (int c = 0; c < 16; c++) {
        if (c < 15) LOAD_CHUNK((c + 1) * 32, (c + 1) & 1);
        CP_COMMIT();
        CP_WAIT1();
        __syncthreads();

        const uint32_t ab = sbase + (uint32_t)(c & 1) * BUF_B;
#pragma unroll
        for (int ks = 0; ks < 2; ks++) {
            uint32_t ah[4][4], al[4][4], bh[2][4], bl[2][4];
            const int kcol = ks * 2 + lcol;
#pragma unroll
            for (int mi = 0; mi < 4; mi++) {
                uint32_t ad = ab + (uint32_t)(((wm * 64 + mi * 16 + lrow) * ASTRIDE) + kcol * 8) * 2;
                ldsm_x4(ah[mi], ad);
                ldsm_x4(al[mi], ad + TILE_B);
            }
#pragma unroll
            for (int nb = 0; nb < 2; nb++) {
                uint32_t bd = ab + 2 * TILE_B +
                              (uint32_t)(((wn * 32 + nb * 16 + lrow) * ASTRIDE) + kcol * 8) * 2;
                ldsm_x4(bh[nb], bd);
                ldsm_x4(bl[nb], bd + TILE_B);
            }
#pragma unroll
            for (int mi = 0; mi < 4; mi++)
#pragma unroll
                for (int ni = 0; ni < 4; ni++) {
                    const int nb = ni >> 1, nl = ni & 1;
                    mma_bf16_16816(acc[mi][ni], ah[mi], bh[nb][nl], bh[nb][nl + 2]);
                    mma_bf16_16816(acc[mi][ni], ah[mi], bl[nb][nl], bl[nb][nl + 2]);
                    mma_bf16_16816(acc[mi][ni], al[mi], bh[nb][nl], bh[nb][nl + 2]);
                }
        }
        __syncthreads();
    }
    CP_WAIT0();
#undef LOAD_CHUNK

    if (EPI == 0) {
#pragma unroll
        for (int mi = 0; mi < 4; mi++) {
            const int r0 = m0 + wm * 64 + mi * 16 + (lane >> 2);
#pragma unroll
            for (int ni = 0; ni < 4; ni++) {
                const int cc = n0 + wn * 32 + ni * 8 + (lane & 3) * 2;
                *(float2*)(C + (size_t)r0 * DMODEL + cc)       = make_float2(acc[mi][ni][0], acc[mi][ni][1]);
                *(float2*)(C + (size_t)(r0 + 8) * DMODEL + cc) = make_float2(acc[mi][ni][2], acc[mi][ni][3]);
            }
        }
    } else {
        // n0 in [0,1536): q fp32 / k fp16 / v fp16
        if (n0 < 512) {
#pragma unroll
            for (int mi = 0; mi < 4; mi++) {
                const int r0 = m0 + wm * 64 + mi * 16 + (lane >> 2);
#pragma unroll
                for (int ni = 0; ni < 4; ni++) {
                    const int cc = n0 + wn * 32 + ni * 8 + (lane & 3) * 2;
                    *(float2*)(C + (size_t)r0 * DMODEL + cc)       = make_float2(acc[mi][ni][0], acc[mi][ni][1]);
                    *(float2*)(C + (size_t)(r0 + 8) * DMODEL + cc) = make_float2(acc[mi][ni][2], acc[mi][ni][3]);
                }
            }
        } else {
            __half* dst = (n0 < 1024) ? K16 : V16;
            const int nb0 = n0 - ((n0 < 1024) ? 512 : 1024);
#pragma unroll
            for (int mi = 0; mi < 4; mi++) {
                const int r0 = m0 + wm * 64 + mi * 16 + (lane >> 2);
#pragma unroll
                for (int ni = 0; ni < 4; ni++) {
                    const int cc = nb0 + wn * 32 + ni * 8 + (lane & 3) * 2;
                    *(__half2*)(dst + (size_t)r0 * DMODEL + cc) =
                        __floats2half2_rn(acc[mi][ni][0], acc[mi][ni][1]);
                    *(__half2*)(dst + (size_t)(r0 + 8) * DMODEL + cc) =
                        __floats2half2_rn(acc[mi][ni][2], acc[mi][ni][3]);
                }
            }
        }
    }
}

__global__ __launch_bounds__(256)
void gemm_qkv(const __nv_bfloat16* __restrict__ Ahi, const __nv_bfloat16* __restrict__ Alo,
              const __nv_bfloat16* __restrict__ Bhi, const __nv_bfloat16* __restrict__ Blo,
              float* __restrict__ Q, __half* __restrict__ K16, __half* __restrict__ V16)
{
    gemm_core<1>(Ahi, Alo, Bhi, Blo, Q, K16, V16);
}

__global__ __launch_bounds__(256)
void gemm_out(const __nv_bfloat16* __restrict__ Ahi, const __nv_bfloat16* __restrict__ Alo,
              const __nv_bfloat16* __restrict__ Bhi, const __nv_bfloat16* __restrict__ Blo,
              float* __restrict__ C)
{
    gemm_core<0>(Ahi, Alo, Bhi, Blo, C, nullptr, nullptr);
}

// ---------------------------------------------------------------------------
// Neighbor attention, fp16 K/V, cp.async double-buffered (K buf0, V buf1).
// One CTA per (b,s); 8 warps = 8 heads. Output written as bf16 hi/lo split.
// ---------------------------------------------------------------------------
#define PITCH_H 520                          // halves; row stride 1040 B
#define ATT_TILE (WNBR * PITCH_H * 2)        // 33280 B
#define ATT_SMEM (2 * ATT_TILE)              // 66560 B

__global__ __launch_bounds__(256)
void attn_kernel(const float* __restrict__ q,
                 const __half* __restrict__ k16,
                 const __half* __restrict__ v16,
                 const int*   __restrict__ nidx,
                 __nv_bfloat16* __restrict__ ahi,
                 __nv_bfloat16* __restrict__ alo)
{
    extern __shared__ char smc[];
    const uint32_t sbase = smem_to_u32(smc);
    __shared__ int   sj[WNBR];
    __shared__ float sq[DMODEL];

    const int bs   = blockIdx.x;
    const int s    = bs & (S_LEN - 1);
    const int b    = bs >> 12;
    const int t    = threadIdx.x;
    const int h    = t >> 5;
    const int lane = t & 31;

    if (t < WNBR) sj[t] = nidx[s * WNBR + t];
    if (t < DMODEL / 4) {
        float4 qv = *(const float4*)(q + (size_t)bs * DMODEL + t * 4);
        *(float4*)(sq + t * 4) = qv;
    }
    __syncthreads();

    // Stage K rows (buf 0) and V rows (buf 1): 32 rows x 1024 B each,
    // 64 16B-chunks per row, 2048 chunks / 256 threads = 8 per thread.
#pragma unroll
    for (int i = 0; i < 8; i++) {
        int e = t + i * 256;
        int w = e >> 6, c = e & 63;
        size_t src = (size_t)(b * S_LEN + sj[w]) * DMODEL + c * 8;
        CP_ASYNC16(sbase + (uint32_t)(w * 1040 + c * 16), k16 + src);
    }
    CP_COMMIT();
#pragma unroll
    for (int i = 0; i < 8; i++) {
        int e = t + i * 256;
        int w = e >> 6, c = e & 63;
        size_t src = (size_t)(b * S_LEN + sj[w]) * DMODEL + c * 8;
        CP_ASYNC16(sbase + ATT_TILE + (uint32_t)(w * 1040 + c * 16), v16 + src);
    }
    CP_COMMIT();

    CP_WAIT1();                              // K tile ready
    __syncthreads();

    // Scores: lane owns neighbor `lane`; 64 halves dot q (fp32)
    float acc = 0.0f;
    {
        const char* kr = smc + lane * 1040 + h * 128;
        const float* qr = sq + h * DHEAD;
#pragma unroll
        for (int i = 0; i < 8; i++) {
            uint4 kv = *(const uint4*)(kr + i * 16);
            float4 q0 = *(const float4*)(qr + i * 8);
            float4 q1 = *(const float4*)(qr + i * 8 + 4);
            float2 f0 = __half22float2(*(__half2*)&kv.x);
            float2 f1 = __half22float2(*(__half2*)&kv.y);
            float2 f2 = __half22float2(*(__half2*)&kv.z);
            float2 f3 = __half22float2(*(__half2*)&kv.w);
            acc += q0.x * f0.x + q0.y * f0.y + q0.z * f1.x + q0.w * f1.y
                 + q1.x * f2.x + q1.y * f2.y + q1.z * f3.x + q1.w * f3.y;
        }
    }
    float score = acc * 0.125f;

    // Warp softmax
    float m = score;
#pragma unroll
    for (int o = 16; o; o >>= 1) m = fmaxf(m, __shfl_xor_sync(0xffffffffu, m, o));
    float e = expf(score - m);
    float ssum = e;
#pragma unroll
    for (int o = 16; o; o >>= 1) ssum += __shfl_xor_sync(0xffffffffu, ssum, o);
    float p = e / ssum;

    CP_WAIT0();                              // V tile ready
    __syncthreads();

    // PV: lane owns d = 2*lane (half2); conflict-free (32 lanes x 4B = 128B)
    float ox = 0.0f, oy = 0.0f;
    const char* vb = smc + ATT_TILE + h * 128 + lane * 4;
#pragma unroll
    for (int w = 0; w < WNBR; w++) {
        float pw = __shfl_sync(0xffffffffu, p, w);
        float2 vv = __half22float2(*(const __half2*)(vb + w * 1040));
        ox += pw * vv.x;
        oy += pw * vv.y;
    }

    // Write output as bf16 hi/lo split (feeds final GEMM directly)
    const size_t oidx = (size_t)bs * DMODEL + h * DHEAD + lane * 2;
    __nv_bfloat16 hx = __float2bfloat16(ox), hy = __float2bfloat16(oy);
    ((__nv_bfloat162*)(ahi + oidx))[0] = __nv_bfloat162(hx, hy);
    ((__nv_bfloat162*)(alo + oidx))[0] =
        __nv_bfloat162(__float2bfloat16(ox - __bfloat162float(hx)),
                       __float2bfloat16(oy - __bfloat162float(hy)));
}

// ---------------------------------------------------------------------------
extern "C" void kernel_launch(void* const* d_in, const int* in_sizes, int n_in,
                              void* d_out, int out_size)
{
    const float* x    = (const float*)d_in[0];
    const float* Wq   = (const float*)d_in[1];
    const float* Wk   = (const float*)d_in[2];
    const float* Wv   = (const float*)d_in[3];
    const float* Wo   = (const float*)d_in[4];
    const int*   nidx = (const int*)  d_in[5];
    float*       out  = (float*)d_out;

    float *q;
    __half *k16, *v16;
    __nv_bfloat16 *ahi, *alo, *whi, *wlo;
    cudaGetSymbolAddress((void**)&q,   g_q);
    cudaGetSymbolAddress((void**)&k16, g_k16);
    cudaGetSymbolAddress((void**)&v16, g_v16);
    cudaGetSymbolAddress((void**)&ahi, g_ahi);
    cudaGetSymbolAddress((void**)&alo, g_alo);
    cudaGetSymbolAddress((void**)&whi, g_whi);
    cudaGetSymbolAddress((void**)&wlo, g_wlo);

    static int attr_set = 0;
    if (!attr_set) {
        cudaFuncSetAttribute(attn_kernel, cudaFuncAttributeMaxDynamicSharedMemorySize, ATT_SMEM);
        cudaFuncSetAttribute(gemm_qkv,    cudaFuncAttributeMaxDynamicSharedMemorySize, GEMM_SMEM);
        cudaFuncSetAttribute(gemm_out,    cudaFuncAttributeMaxDynamicSharedMemorySize, GEMM_SMEM);
        attr_set = 1;
    }

    const int NW  = DMODEL * DMODEL;          // 262144
    const int nx4 = M_TOT * DMODEL / 4;       // 1048576

    // Splits: x (activations) + all 4 weights (one fused launch)
    split_kernel<<<(nx4 + 255) / 256, 256>>>(x, ahi, alo, nx4);
    split4_kernel<<<(4 * NW / 4) / 256, 256>>>(Wq, Wk, Wv, Wo, whi, wlo);

    // Fused QKV GEMM: B rows 0..1535 of concatenated weights
    dim3 qkvgrid(3 * DMODEL / 128, M_TOT / 128);   // (12, 64)
    gemm_qkv<<<qkvgrid, 256, GEMM_SMEM>>>(ahi, alo, whi, wlo, q, k16, v16);

    attn_kernel<<<M_TOT, 256, ATT_SMEM>>>(q, k16, v16, nidx, ahi, alo);

    dim3 ogrid(DMODEL / 128, M_TOT / 128);         // (4, 64)
    gemm_out<<<ogrid, 256, GEMM_SMEM>>>(ahi, alo, whi + 3 * NW, wlo + 3 * NW, out);
}

// round 5
// speedup vs baseline: 3.5634x; 1.3370x over previous
#include <cuda_runtime.h>
#include <cuda_fp16.h>
#include <cstdint>

// Problem constants
#define BATCH   2
#define S_LEN   4096
#define DMODEL  512
#define NHEAD   8
#define DHEAD   64
#define WNBR    32
#define M_TOT   (BATCH * S_LEN)      // 8192

// ---------------------------------------------------------------------------
// PTX helpers — base sm_103 only (NO tcgen05)
// ---------------------------------------------------------------------------
__device__ __forceinline__ uint32_t smem_to_u32(const void* p) {
    uint32_t a;
    asm("{ .reg .u64 t; cvta.to.shared.u64 t, %1; cvt.u32.u64 %0, t; }" : "=r"(a) : "l"(p));
    return a;
}
__device__ __forceinline__ void ldsm_x4(uint32_t* r, uint32_t addr) {
    asm volatile("ldmatrix.sync.aligned.m8n8.x4.shared.b16 {%0,%1,%2,%3}, [%4];"
                 : "=r"(r[0]), "=r"(r[1]), "=r"(r[2]), "=r"(r[3]) : "r"(addr));
}
__device__ __forceinline__ void mma_f16_16816(float* d, const uint32_t* a,
                                              uint32_t b0, uint32_t b1) {
    asm volatile(
        "mma.sync.aligned.m16n8k16.row.col.f32.f16.f16.f32 "
        "{%0,%1,%2,%3}, {%4,%5,%6,%7}, {%8,%9}, {%0,%1,%2,%3};"
        : "+f"(d[0]), "+f"(d[1]), "+f"(d[2]), "+f"(d[3])
        : "r"(a[0]), "r"(a[1]), "r"(a[2]), "r"(a[3]), "r"(b0), "r"(b1));
}
#define CP_ASYNC16(sa, gp) \
    asm volatile("cp.async.cg.shared.global [%0], [%1], 16;" :: "r"(sa), "l"(gp))
#define CP_COMMIT() asm volatile("cp.async.commit_group;")
#define CP_WAIT1()  asm volatile("cp.async.wait_group 1;")
#define CP_WAIT0()  asm volatile("cp.async.wait_group 0;")

// ---------------------------------------------------------------------------
// Scratch (allocation-free rule: device globals)
// ---------------------------------------------------------------------------
__device__ float g_q[M_TOT * DMODEL];                     // Q fp32
__device__ __align__(256) __half g_k16[M_TOT * DMODEL];   // K fp16
__device__ __align__(256) __half g_v16[M_TOT * DMODEL];   // V fp16
__device__ __align__(256) __half g_ahi[M_TOT * DMODEL];   // A-operand hi (x, later attn-out)
__device__ __align__(256) __half g_alo[M_TOT * DMODEL];   // A-operand lo
// weights fp16: rows 0..511 Wq, 512..1023 Wk, 1024..1535 Wv, 1536..2047 Wo
__device__ __align__(256) __half g_w16[4 * DMODEL * DMODEL];

// ---------------------------------------------------------------------------
// fp32 -> (fp16 hi, fp16 lo) split for the GEMM A-operand
// ---------------------------------------------------------------------------
__global__ __launch_bounds__(256)
void split_kernel(const float* __restrict__ in,
                  __half* __restrict__ hi, __half* __restrict__ lo, int n4)
{
    int i = blockIdx.x * blockDim.x + threadIdx.x;
    if (i >= n4) return;
    float4 x = ((const float4*)in)[i];
    __half h0 = __float2half_rn(x.x), h1 = __float2half_rn(x.y);
    __half h2 = __float2half_rn(x.z), h3 = __float2half_rn(x.w);
    ((__half2*)hi)[i * 2 + 0] = __halves2half2(h0, h1);
    ((__half2*)hi)[i * 2 + 1] = __halves2half2(h2, h3);
    ((__half2*)lo)[i * 2 + 0] = __halves2half2(__float2half_rn(x.x - __half2float(h0)),
                                               __float2half_rn(x.y - __half2float(h1)));
    ((__half2*)lo)[i * 2 + 1] = __halves2half2(__float2half_rn(x.z - __half2float(h2)),
                                               __float2half_rn(x.w - __half2float(h3)));
}

// Fused fp32 -> fp16 convert of the 4 weight matrices (concatenated)
__global__ __launch_bounds__(256)
void convert4_kernel(const float* __restrict__ w0, const float* __restrict__ w1,
                     const float* __restrict__ w2, const float* __restrict__ w3,
                     __half* __restrict__ dst)
{
    int i = blockIdx.x * blockDim.x + threadIdx.x;   // 0 .. 4*65536-1
    int w = i >> 16, l = i & 65535;
    const float* src = (w == 0) ? w0 : (w == 1) ? w1 : (w == 2) ? w2 : w3;
    float4 x = ((const float4*)src)[l];
    ((__half2*)dst)[i * 2 + 0] = __floats2half2_rn(x.x, x.y);
    ((__half2*)dst)[i * 2 + 1] = __floats2half2_rn(x.z, x.w);
}

// ---------------------------------------------------------------------------
// HMMA fp16x2 GEMM core: C = (Ahi + Alo) * B^T, 2 MMAs per fragment.
// CTA 128x128, BK=32, 256 threads, warp grid 2(M) x 4(N), warp tile 64x32.
// Smem rows padded to 40 halves (80B). cp.async double buffer, 16 K-chunks.
// EPI: 0 = fp32 C ; 1 = QKV (q fp32 / k,v fp16 by n0 block)
// ---------------------------------------------------------------------------
#define ASTRIDE 40
#define TILE_B  (128 * ASTRIDE * 2)   // 10240 B per 128x32 tile
#define BUF_B   (3 * TILE_B)          // Ahi|Alo|B = 30720
#define GEMM_SMEM (2 * BUF_B)         // 61440

template <int EPI>
__device__ __forceinline__
void gemm_core(const __half* __restrict__ Ahi, const __half* __restrict__ Alo,
               const __half* __restrict__ B,
               float* __restrict__ C, __half* __restrict__ K16, __half* __restrict__ V16)
{
    extern __shared__ char smc[];
    const uint32_t sbase = smem_to_u32(smc);
    const int t = threadIdx.x, lane = t & 31, wid = t >> 5;
    const int wm = wid & 1, wn = wid >> 1;
    const int m0 = blockIdx.y * 128;
    const int n0 = blockIdx.x * 128;

    float acc[4][4][4];
#pragma unroll
    for (int mi = 0; mi < 4; mi++)
#pragma unroll
        for (int ni = 0; ni < 4; ni++)
#pragma unroll
            for (int j = 0; j < 4; j++) acc[mi][ni][j] = 0.0f;

    const int e0row = t >> 2,         e0c = (t & 3) * 8;
    const int e1row = (t + 256) >> 2, e1c = ((t + 256) & 3) * 8;
    const uint32_t so0 = (uint32_t)(e0row * ASTRIDE + e0c) * 2;
    const uint32_t so1 = (uint32_t)(e1row * ASTRIDE + e1c) * 2;

#define LOAD_CHUNK(kc, buf) do { \
    uint32_t bb = sbase + (uint32_t)(buf) * BUF_B; \
    size_t ga0 = (size_t)(m0 + e0row) * DMODEL + (kc) + e0c; \
    size_t ga1 = (size_t)(m0 + e1row) * DMODEL + (kc) + e1c; \
    size_t gb0 = (size_t)(n0 + e0row) * DMODEL + (kc) + e0c; \
    size_t gb1 = (size_t)(n0 + e1row) * DMODEL + (kc) + e1c; \
    CP_ASYNC16(bb + so0,              Ahi + ga0); \
    CP_ASYNC16(bb + so1,              Ahi + ga1); \
    CP_ASYNC16(bb + TILE_B + so0,     Alo + ga0); \
    CP_ASYNC16(bb + TILE_B + so1,     Alo + ga1); \
    CP_ASYNC16(bb + 2 * TILE_B + so0, B + gb0); \
    CP_ASYNC16(bb + 2 * TILE_B + so1, B + gb1); \
} while (0)

    LOAD_CHUNK(0, 0);
    CP_COMMIT();

    const int lrow = lane & 15;
    const int lcol = lane >> 4;

    for (int c = 0; c < 16; c++) {
        if (c < 15) LOAD_CHUNK((c + 1) * 32, (c + 1) & 1);
        CP_COMMIT();
        CP_WAIT1();
        __syncthreads();

        const uint32_t ab = sbase + (uint32_t)(c & 1) * BUF_B;
#pragma unroll
        for (int ks = 0; ks < 2; ks++) {
            uint32_t ah[4][4], al[4][4], bf[2][4];
            const int kcol = ks * 2 + lcol;
#pragma unroll
            for (int mi = 0; mi < 4; mi++) {
                uint32_t ad = ab + (uint32_t)(((wm * 64 + mi * 16 + lrow) * ASTRIDE) + kcol * 8) * 2;
                ldsm_x4(ah[mi], ad);
                ldsm_x4(al[mi], ad + TILE_B);
            }
#pragma unroll
            for (int nb = 0; nb < 2; nb++) {
                uint32_t bd = ab + 2 * TILE_B +
                              (uint32_t)(((wn * 32 + nb * 16 + lrow) * ASTRIDE) + kcol * 8) * 2;
                ldsm_x4(bf[nb], bd);
            }
#pragma unroll
            for (int mi = 0; mi < 4; mi++)
#pragma unroll
                for (int ni = 0; ni < 4; ni++) {
                    const int nb = ni >> 1, nl = ni & 1;
                    mma_f16_16816(acc[mi][ni], ah[mi], bf[nb][nl], bf[nb][nl + 2]);
                    mma_f16_16816(acc[mi][ni], al[mi], bf[nb][nl], bf[nb][nl + 2]);
                }
        }
        __syncthreads();
    }
    CP_WAIT0();
#undef LOAD_CHUNK

    if (EPI == 0 || (EPI == 1 && n0 < 512)) {
#pragma unroll
        for (int mi = 0; mi < 4; mi++) {
            const int r0 = m0 + wm * 64 + mi * 16 + (lane >> 2);
#pragma unroll
            for (int ni = 0; ni < 4; ni++) {
                const int cc = n0 + wn * 32 + ni * 8 + (lane & 3) * 2;
                *(float2*)(C + (size_t)r0 * DMODEL + cc)       = make_float2(acc[mi][ni][0], acc[mi][ni][1]);
                *(float2*)(C + (size_t)(r0 + 8) * DMODEL + cc) = make_float2(acc[mi][ni][2], acc[mi][ni][3]);
            }
        }
    } else {
        __half* dst = (n0 < 1024) ? K16 : V16;
        const int nb0 = n0 - ((n0 < 1024) ? 512 : 1024);
#pragma unroll
        for (int mi = 0; mi < 4; mi++) {
            const int r0 = m0 + wm * 64 + mi * 16 + (lane >> 2);
#pragma unroll
            for (int ni = 0; ni < 4; ni++) {
                const int cc = nb0 + wn * 32 + ni * 8 + (lane & 3) * 2;
                *(__half2*)(dst + (size_t)r0 * DMODEL + cc) =
                    __floats2half2_rn(acc[mi][ni][0], acc[mi][ni][1]);
                *(__half2*)(dst + (size_t)(r0 + 8) * DMODEL + cc) =
                    __floats2half2_rn(acc[mi][ni][2], acc[mi][ni][3]);
            }
        }
    }
}

__global__ __launch_bounds__(256, 2)
void gemm_qkv(const __half* __restrict__ Ahi, const __half* __restrict__ Alo,
              const __half* __restrict__ B,
              float* __restrict__ Q, __half* __restrict__ K16, __half* __restrict__ V16)
{
    gemm_core<1>(Ahi, Alo, B, Q, K16, V16);
}

__global__ __launch_bounds__(256, 2)
void gemm_out(const __half* __restrict__ Ahi, const __half* __restrict__ Alo,
              const __half* __restrict__ B, float* __restrict__ C)
{
    gemm_core<0>(Ahi, Alo, B, C, nullptr, nullptr);
}

// ---------------------------------------------------------------------------
// Neighbor attention: K staged via cp.async (33 KB smem), V gathered directly
// from L2 per-warp after softmax (coalesced 128B per (w,h)). One CTA per
// (b,s); 8 warps = 8 heads. Output written as fp16 hi/lo split.
// ---------------------------------------------------------------------------
#define PITCH_H 520                          // halves; row stride 1040 B
#define ATT_SMEM (WNBR * PITCH_H * 2)        // 33280 B

__global__ __launch_bounds__(256, 6)
void attn_kernel(const float* __restrict__ q,
                 const __half* __restrict__ k16,
                 const __half* __restrict__ v16,
                 const int*   __restrict__ nidx,
                 __half* __restrict__ ahi,
                 __half* __restrict__ alo)
{
    extern __shared__ char smc[];
    const uint32_t sbase = smem_to_u32(smc);
    __shared__ int   sj[WNBR];
    __shared__ float sq[DMODEL];

    const int bs   = blockIdx.x;
    const int s    = bs & (S_LEN - 1);
    const int b    = bs >> 12;
    const int t    = threadIdx.x;
    const int h    = t >> 5;
    const int lane = t & 31;

    if (t < WNBR) sj[t] = nidx[s * WNBR + t];
    if (t < DMODEL / 4) {
        float4 qv = *(const float4*)(q + (size_t)bs * DMODEL + t * 4);
        *(float4*)(sq + t * 4) = qv;
    }
    __syncthreads();

    // Stage K rows: 32 rows x 1024 B, 64 16B-chunks per row, 8 per thread.
#pragma unroll
    for (int i = 0; i < 8; i++) {
        int e = t + i * 256;
        int w = e >> 6, c = e & 63;
        size_t src = (size_t)(b * S_LEN + sj[w]) * DMODEL + c * 8;
        CP_ASYNC16(sbase + (uint32_t)(w * 1040 + c * 16), k16 + src);
    }
    CP_COMMIT();
    CP_WAIT0();
    __syncthreads();

    // Scores: lane owns neighbor `lane`
    float acc = 0.0f;
    {
        const char* kr = smc + lane * 1040 + h * 128;
        const float* qr = sq + h * DHEAD;
#pragma unroll
        for (int i = 0; i < 8; i++) {
            uint4 kv = *(const uint4*)(kr + i * 16);
            float4 q0 = *(const float4*)(qr + i * 8);
            float4 q1 = *(const float4*)(qr + i * 8 + 4);
            float2 f0 = __half22float2(*(__half2*)&kv.x);
            float2 f1 = __half22float2(*(__half2*)&kv.y);
            float2 f2 = __half22float2(*(__half2*)&kv.z);
            float2 f3 = __half22float2(*(__half2*)&kv.w);
            acc += q0.x * f0.x + q0.y * f0.y + q0.z * f1.x + q0.w * f1.y
                 + q1.x * f2.x + q1.y * f2.y + q1.z * f3.x + q1.w * f3.y;
        }
    }
    float score = acc * 0.125f;

    // Warp softmax
    float m = score;
#pragma unroll
    for (int o = 16; o; o >>= 1) m = fmaxf(m, __shfl_xor_sync(0xffffffffu, m, o));
    float e = expf(score - m);
    float ssum = e;
#pragma unroll
    for (int o = 16; o; o >>= 1) ssum += __shfl_xor_sync(0xffffffffu, ssum, o);
    float p = e / ssum;

    // PV: direct L2 gather, 8-deep load batches for MLP
    float ox = 0.0f, oy = 0.0f;
    const __half* vbase = v16 + (size_t)b * S_LEN * DMODEL + h * DHEAD + lane * 2;
#pragma unroll
    for (int w0 = 0; w0 < WNBR; w0 += 8) {
        float2 vv[8];
#pragma unroll
        for (int u = 0; u < 8; u++)
            vv[u] = __half22float2(*(const __half2*)(vbase + (size_t)sj[w0 + u] * DMODEL));
#pragma unroll
        for (int u = 0; u < 8; u++) {
            float pw = __shfl_sync(0xffffffffu, p, w0 + u);
            ox += pw * vv[u].x;
            oy += pw * vv[u].y;
        }
    }

    // Write output as fp16 hi/lo split (feeds final GEMM directly)
    const size_t oidx = (size_t)bs * DMODEL + h * DHEAD + lane * 2;
    __half hx = __float2half_rn(ox), hy = __float2half_rn(oy);
    *(__half2*)(ahi + oidx) = __halves2half2(hx, hy);
    *(__half2*)(alo + oidx) = __halves2half2(__float2half_rn(ox - __half2float(hx)),
                                             __float2half_rn(oy - __half2float(hy)));
}

// ---------------------------------------------------------------------------
extern "C" void kernel_launch(void* const* d_in, const int* in_sizes, int n_in,
                              void* d_out, int out_size)
{
    const float* x    = (const float*)d_in[0];
    const float* Wq   = (const float*)d_in[1];
    const float* Wk   = (const float*)d_in[2];
    const float* Wv   = (const float*)d_in[3];
    const float* Wo   = (const float*)d_in[4];
    const int*   nidx = (const int*)  d_in[5];
    float*       out  = (float*)d_out;

    float *q;
    __half *k16, *v16, *ahi, *alo, *w16;
    cudaGetSymbolAddress((void**)&q,   g_q);
    cudaGetSymbolAddress((void**)&k16, g_k16);
    cudaGetSymbolAddress((void**)&v16, g_v16);
    cudaGetSymbolAddress((void**)&ahi, g_ahi);
    cudaGetSymbolAddress((void**)&alo, g_alo);
    cudaGetSymbolAddress((void**)&w16, g_w16);

    static int attr_set = 0;
    if (!attr_set) {
        cudaFuncSetAttribute(attn_kernel, cudaFuncAttributeMaxDynamicSharedMemorySize, ATT_SMEM);
        cudaFuncSetAttribute(gemm_qkv,    cudaFuncAttributeMaxDynamicSharedMemorySize, GEMM_SMEM);
        cudaFuncSetAttribute(gemm_out,    cudaFuncAttributeMaxDynamicSharedMemorySize, GEMM_SMEM);
        attr_set = 1;
    }

    const int NW  = DMODEL * DMODEL;          // 262144
    const int nx4 = M_TOT * DMODEL / 4;       // 1048576

    split_kernel<<<(nx4 + 255) / 256, 256>>>(x, ahi, alo, nx4);
    convert4_kernel<<<(4 * NW / 4) / 256, 256>>>(Wq, Wk, Wv, Wo, w16);

    dim3 qkvgrid(3 * DMODEL / 128, M_TOT / 128);   // (12, 64)
    gemm_qkv<<<qkvgrid, 256, GEMM_SMEM>>>(ahi, alo, w16, q, k16, v16);

    attn_kernel<<<M_TOT, 256, ATT_SMEM>>>(q, k16, v16, nidx, ahi, alo);

    dim3 ogrid(DMODEL / 128, M_TOT / 128);         // (4, 64)
    gemm_out<<<ogrid, 256, GEMM_SMEM>>>(ahi, alo, w16 + 3 * NW, out);
}

// round 6
// speedup vs baseline: 4.9996x; 1.4030x over previous
#include <cuda_runtime.h>
#include <cuda_fp16.h>
#include <cstdint>

// Problem constants
#define BATCH   2
#define S_LEN   4096
#define DMODEL  512
#define NHEAD   8
#define DHEAD   64
#define WNBR    32
#define M_TOT   (BATCH * S_LEN)      // 8192

// ---------------------------------------------------------------------------
// PTX helpers — base sm_103 only (NO tcgen05)
// ---------------------------------------------------------------------------
__device__ __forceinline__ uint32_t smem_to_u32(const void* p) {
    uint32_t a;
    asm("{ .reg .u64 t; cvta.to.shared.u64 t, %1; cvt.u32.u64 %0, t; }" : "=r"(a) : "l"(p));
    return a;
}
__device__ __forceinline__ void ldsm_x4(uint32_t* r, uint32_t addr) {
    asm volatile("ldmatrix.sync.aligned.m8n8.x4.shared.b16 {%0,%1,%2,%3}, [%4];"
                 : "=r"(r[0]), "=r"(r[1]), "=r"(r[2]), "=r"(r[3]) : "r"(addr));
}
__device__ __forceinline__ void mma_f16_16816(float* d, const uint32_t* a,
                                              uint32_t b0, uint32_t b1) {
    asm volatile(
        "mma.sync.aligned.m16n8k16.row.col.f32.f16.f16.f32 "
        "{%0,%1,%2,%3}, {%4,%5,%6,%7}, {%8,%9}, {%0,%1,%2,%3};"
        : "+f"(d[0]), "+f"(d[1]), "+f"(d[2]), "+f"(d[3])
        : "r"(a[0]), "r"(a[1]), "r"(a[2]), "r"(a[3]), "r"(b0), "r"(b1));
}
#define CP_ASYNC16(sa, gp) \
    asm volatile("cp.async.cg.shared.global [%0], [%1], 16;" :: "r"(sa), "l"(gp))
#define CP_COMMIT() asm volatile("cp.async.commit_group;")
#define CP_WAIT1()  asm volatile("cp.async.wait_group 1;")
#define CP_WAIT0()  asm volatile("cp.async.wait_group 0;")

// ---------------------------------------------------------------------------
// Scratch (allocation-free rule: device globals)
// ---------------------------------------------------------------------------
__device__ float g_q[M_TOT * DMODEL];                     // Q fp32
__device__ __align__(256) __half g_k16[M_TOT * DMODEL];   // K fp16
__device__ __align__(256) __half g_v16[M_TOT * DMODEL];   // V fp16
__device__ __align__(256) __half g_x16[M_TOT * DMODEL];   // x fp16 (later attn-out)
// weights fp16: rows 0..511 Wq, 512..1023 Wk, 1024..1535 Wv, 1536..2047 Wo
__device__ __align__(256) __half g_w16[4 * DMODEL * DMODEL];

// ---------------------------------------------------------------------------
// Fused prep: convert x (nx4 float4s) and the 4 weight matrices to fp16
// ---------------------------------------------------------------------------
#define NX4  (M_TOT * DMODEL / 4)            // 1048576
#define NW4  (DMODEL * DMODEL / 4)           // 65536

__global__ __launch_bounds__(256)
void prep_kernel(const float* __restrict__ x,
                 const float* __restrict__ w0, const float* __restrict__ w1,
                 const float* __restrict__ w2, const float* __restrict__ w3,
                 __half* __restrict__ x16, __half* __restrict__ w16)
{
    int i = blockIdx.x * blockDim.x + threadIdx.x;
    const float* src;
    __half* dst;
    int l;
    if (i < NX4) {
        src = x; dst = x16; l = i;
    } else {
        int j = i - NX4;
        int w = j >> 16;  l = j & (NW4 - 1);
        src = (w == 0) ? w0 : (w == 1) ? w1 : (w == 2) ? w2 : w3;
        dst = w16 + (size_t)w * DMODEL * DMODEL;
    }
    float4 v = ((const float4*)src)[l];
    ((__half2*)dst)[l * 2 + 0] = __floats2half2_rn(v.x, v.y);
    ((__half2*)dst)[l * 2 + 1] = __floats2half2_rn(v.z, v.w);
}

// ---------------------------------------------------------------------------
// Pure fp16 HMMA GEMM: C = A * B^T (row-major, K-major), fp32 accum.
// CTA 128x128, BK=32, 256 threads, warp grid 2(M) x 4(N), warp tile 64x32.
// Smem rows padded to 40 halves (80B). cp.async double buffer, 16 K-chunks.
// EPI: 0 = fp32 C ; 1 = QKV (q fp32 / k,v fp16 by n0 block)
// ---------------------------------------------------------------------------
#define ASTRIDE 40
#define TILE_B  (128 * ASTRIDE * 2)   // 10240 B per 128x32 tile
#define BUF_B   (2 * TILE_B)          // A|B = 20480
#define GEMM_SMEM (2 * BUF_B)         // 40960

template <int EPI>
__device__ __forceinline__
void gemm_core(const __half* __restrict__ A, const __half* __restrict__ B,
               float* __restrict__ C, __half* __restrict__ K16, __half* __restrict__ V16)
{
    extern __shared__ char smc[];
    const uint32_t sbase = smem_to_u32(smc);
    const int t = threadIdx.x, lane = t & 31, wid = t >> 5;
    const int wm = wid & 1, wn = wid >> 1;
    const int m0 = blockIdx.y * 128;
    const int n0 = blockIdx.x * 128;

    float acc[4][4][4];
#pragma unroll
    for (int mi = 0; mi < 4; mi++)
#pragma unroll
        for (int ni = 0; ni < 4; ni++)
#pragma unroll
            for (int j = 0; j < 4; j++) acc[mi][ni][j] = 0.0f;

    const int e0row = t >> 2,         e0c = (t & 3) * 8;
    const int e1row = (t + 256) >> 2, e1c = ((t + 256) & 3) * 8;
    const uint32_t so0 = (uint32_t)(e0row * ASTRIDE + e0c) * 2;
    const uint32_t so1 = (uint32_t)(e1row * ASTRIDE + e1c) * 2;

#define LOAD_CHUNK(kc, buf) do { \
    uint32_t bb = sbase + (uint32_t)(buf) * BUF_B; \
    size_t ga0 = (size_t)(m0 + e0row) * DMODEL + (kc) + e0c; \
    size_t ga1 = (size_t)(m0 + e1row) * DMODEL + (kc) + e1c; \
    size_t gb0 = (size_t)(n0 + e0row) * DMODEL + (kc) + e0c; \
    size_t gb1 = (size_t)(n0 + e1row) * DMODEL + (kc) + e1c; \
    CP_ASYNC16(bb + so0,          A + ga0); \
    CP_ASYNC16(bb + so1,          A + ga1); \
    CP_ASYNC16(bb + TILE_B + so0, B + gb0); \
    CP_ASYNC16(bb + TILE_B + so1, B + gb1); \
} while (0)

    LOAD_CHUNK(0, 0);
    CP_COMMIT();

    const int lrow = lane & 15;
    const int lcol = lane >> 4;

    for (int c = 0; c < 16; c++) {
        if (c < 15) LOAD_CHUNK((c + 1) * 32, (c + 1) & 1);
        CP_COMMIT();
        CP_WAIT1();
        __syncthreads();

        const uint32_t ab = sbase + (uint32_t)(c & 1) * BUF_B;
#pragma unroll
        for (int ks = 0; ks < 2; ks++) {
            uint32_t af[4][4], bf[2][4];
            const int kcol = ks * 2 + lcol;
#pragma unroll
            for (int mi = 0; mi < 4; mi++) {
                uint32_t ad = ab + (uint32_t)(((wm * 64 + mi * 16 + lrow) * ASTRIDE) + kcol * 8) * 2;
                ldsm_x4(af[mi], ad);
            }
#pragma unroll
            for (int nb = 0; nb < 2; nb++) {
                uint32_t bd = ab + TILE_B +
                              (uint32_t)(((wn * 32 + nb * 16 + lrow) * ASTRIDE) + kcol * 8) * 2;
                ldsm_x4(bf[nb], bd);
            }
#pragma unroll
            for (int mi = 0; mi < 4; mi++)
#pragma unroll
                for (int ni = 0; ni < 4; ni++) {
                    const int nb = ni >> 1, nl = ni & 1;
                    mma_f16_16816(acc[mi][ni], af[mi], bf[nb][nl], bf[nb][nl + 2]);
                }
        }
        __syncthreads();
    }
    CP_WAIT0();
#undef LOAD_CHUNK

    if (EPI == 0 || (EPI == 1 && n0 < 512)) {
#pragma unroll
        for (int mi = 0; mi < 4; mi++) {
            const int r0 = m0 + wm * 64 + mi * 16 + (lane >> 2);
#pragma unroll
            for (int ni = 0; ni < 4; ni++) {
                const int cc = n0 + wn * 32 + ni * 8 + (lane & 3) * 2;
                *(float2*)(C + (size_t)r0 * DMODEL + cc)       = make_float2(acc[mi][ni][0], acc[mi][ni][1]);
                *(float2*)(C + (size_t)(r0 + 8) * DMODEL + cc) = make_float2(acc[mi][ni][2], acc[mi][ni][3]);
            }
        }
    } else {
        __half* dst = (n0 < 1024) ? K16 : V16;
        const int nb0 = n0 - ((n0 < 1024) ? 512 : 1024);
#pragma unroll
        for (int mi = 0; mi < 4; mi++) {
            const int r0 = m0 + wm * 64 + mi * 16 + (lane >> 2);
#pragma unroll
            for (int ni = 0; ni < 4; ni++) {
                const int cc = nb0 + wn * 32 + ni * 8 + (lane & 3) * 2;
                *(__half2*)(dst + (size_t)r0 * DMODEL + cc) =
                    __floats2half2_rn(acc[mi][ni][0], acc[mi][ni][1]);
                *(__half2*)(dst + (size_t)(r0 + 8) * DMODEL + cc) =
                    __floats2half2_rn(acc[mi][ni][2], acc[mi][ni][3]);
            }
        }
    }
}

__global__ __launch_bounds__(256, 2)
void gemm_qkv(const __half* __restrict__ A, const __half* __restrict__ B,
              float* __restrict__ Q, __half* __restrict__ K16, __half* __restrict__ V16)
{
    gemm_core<1>(A, B, Q, K16, V16);
}

__global__ __launch_bounds__(256, 2)
void gemm_out(const __half* __restrict__ A, const __half* __restrict__ B,
              float* __restrict__ C)
{
    gemm_core<0>(A, B, C, nullptr, nullptr);
}

// ---------------------------------------------------------------------------
// Neighbor attention: K staged via cp.async (33 KB smem), V gathered directly
// from L2 per-warp (first 2 batches issued before softmax to hide latency).
// One CTA per (b,s); 8 warps = 8 heads. Output written as fp16.
// ---------------------------------------------------------------------------
#define PITCH_H 520                          // halves; row stride 1040 B
#define ATT_SMEM (WNBR * PITCH_H * 2)        // 33280 B

__global__ __launch_bounds__(256, 6)
void attn_kernel(const float* __restrict__ q,
                 const __half* __restrict__ k16,
                 const __half* __restrict__ v16,
                 const int*   __restrict__ nidx,
                 __half* __restrict__ a16)
{
    extern __shared__ char smc[];
    const uint32_t sbase = smem_to_u32(smc);
    __shared__ int   sj[WNBR];
    __shared__ float sq[DMODEL];

    const int bs   = blockIdx.x;
    const int s    = bs & (S_LEN - 1);
    const int b    = bs >> 12;
    const int t    = threadIdx.x;
    const int h    = t >> 5;
    const int lane = t & 31;

    if (t < WNBR) sj[t] = nidx[s * WNBR + t];
    if (t < DMODEL / 4) {
        float4 qv = *(const float4*)(q + (size_t)bs * DMODEL + t * 4);
        *(float4*)(sq + t * 4) = qv;
    }
    __syncthreads();

    // Stage K rows: 32 rows x 1024 B, 64 16B-chunks per row, 8 per thread.
#pragma unroll
    for (int i = 0; i < 8; i++) {
        int e = t + i * 256;
        int w = e >> 6, c = e & 63;
        size_t src = (size_t)(b * S_LEN + sj[w]) * DMODEL + c * 8;
        CP_ASYNC16(sbase + (uint32_t)(w * 1040 + c * 16), k16 + src);
    }
    CP_COMMIT();
    CP_WAIT0();
    __syncthreads();

    // Scores: lane owns neighbor `lane`
    float acc = 0.0f;
    {
        const char* kr = smc + lane * 1040 + h * 128;
        const float* qr = sq + h * DHEAD;
#pragma unroll
        for (int i = 0; i < 8; i++) {
            uint4 kv = *(const uint4*)(kr + i * 16);
            float4 q0 = *(const float4*)(qr + i * 8);
            float4 q1 = *(const float4*)(qr + i * 8 + 4);
            float2 f0 = __half22float2(*(__half2*)&kv.x);
            float2 f1 = __half22float2(*(__half2*)&kv.y);
            float2 f2 = __half22float2(*(__half2*)&kv.z);
            float2 f3 = __half22float2(*(__half2*)&kv.w);
            acc += q0.x * f0.x + q0.y * f0.y + q0.z * f1.x + q0.w * f1.y
                 + q1.x * f2.x + q1.y * f2.y + q1.z * f3.x + q1.w * f3.y;
        }
    }
    float score = acc * 0.125f;

    // Prefetch V batches 0,1 (depend only on sj) before the softmax chain
    const __half* vbase = v16 + (size_t)b * S_LEN * DMODEL + h * DHEAD + lane * 2;
    float2 vpre[16];
#pragma unroll
    for (int u = 0; u < 16; u++)
        vpre[u] = __half22float2(*(const __half2*)(vbase + (size_t)sj[u] * DMODEL));

    // Warp softmax
    float m = score;
#pragma unroll
    for (int o = 16; o; o >>= 1) m = fmaxf(m, __shfl_xor_sync(0xffffffffu, m, o));
    float e = expf(score - m);
    float ssum = e;
#pragma unroll
    for (int o = 16; o; o >>= 1) ssum += __shfl_xor_sync(0xffffffffu, ssum, o);
    float p = e / ssum;

    // PV: prefetched batches first, then the remaining two 8-deep batches
    float ox = 0.0f, oy = 0.0f;
#pragma unroll
    for (int u = 0; u < 16; u++) {
        float pw = __shfl_sync(0xffffffffu, p, u);
        ox += pw * vpre[u].x;
        oy += pw * vpre[u].y;
    }
#pragma unroll
    for (int w0 = 16; w0 < WNBR; w0 += 8) {
        float2 vv[8];
#pragma unroll
        for (int u = 0; u < 8; u++)
            vv[u] = __half22float2(*(const __half2*)(vbase + (size_t)sj[w0 + u] * DMODEL));
#pragma unroll
        for (int u = 0; u < 8; u++) {
            float pw = __shfl_sync(0xffffffffu, p, w0 + u);
            ox += pw * vv[u].x;
            oy += pw * vv[u].y;
        }
    }

    // fp16 output (feeds final GEMM directly)
    const size_t oidx = (size_t)bs * DMODEL + h * DHEAD + lane * 2;
    *(__half2*)(a16 + oidx) = __floats2half2_rn(ox, oy);
}

// ---------------------------------------------------------------------------
extern "C" void kernel_launch(void* const* d_in, const int* in_sizes, int n_in,
                              void* d_out, int out_size)
{
    const float* x    = (const float*)d_in[0];
    const float* Wq   = (const float*)d_in[1];
    const float* Wk   = (const float*)d_in[2];
    const float* Wv   = (const float*)d_in[3];
    const float* Wo   = (const float*)d_in[4];
    const int*   nidx = (const int*)  d_in[5];
    float*       out  = (float*)d_out;

    float *q;
    __half *k16, *v16, *x16, *w16;
    cudaGetSymbolAddress((void**)&q,   g_q);
    cudaGetSymbolAddress((void**)&k16, g_k16);
    cudaGetSymbolAddress((void**)&v16, g_v16);
    cudaGetSymbolAddress((void**)&x16, g_x16);
    cudaGetSymbolAddress((void**)&w16, g_w16);

    static int attr_set = 0;
    if (!attr_set) {
        cudaFuncSetAttribute(attn_kernel, cudaFuncAttributeMaxDynamicSharedMemorySize, ATT_SMEM);
        cudaFuncSetAttribute(gemm_qkv,    cudaFuncAttributeMaxDynamicSharedMemorySize, GEMM_SMEM);
        cudaFuncSetAttribute(gemm_out,    cudaFuncAttributeMaxDynamicSharedMemorySize, GEMM_SMEM);
        attr_set = 1;
    }

    const int NW = DMODEL * DMODEL;           // 262144

    prep_kernel<<<(NX4 + 4 * NW4) / 256, 256>>>(x, Wq, Wk, Wv, Wo, x16, w16);

    dim3 qkvgrid(3 * DMODEL / 128, M_TOT / 128);   // (12, 64)
    gemm_qkv<<<qkvgrid, 256, GEMM_SMEM>>>(x16, w16, q, k16, v16);

    attn_kernel<<<M_TOT, 256, ATT_SMEM>>>(q, k16, v16, nidx, x16);

    dim3 ogrid(DMODEL / 128, M_TOT / 128);         // (4, 64)
    gemm_out<<<ogrid, 256, GEMM_SMEM>>>(x16, w16 + 3 * NW, out);
}

// round 8
// speedup vs baseline: 5.3660x; 1.0733x over previous
#include <cuda_runtime.h>
#include <cuda_fp16.h>
#include <cstdint>

// Problem constants
#define BATCH   2
#define S_LEN   4096
#define DMODEL  512
#define NHEAD   8
#define DHEAD   64
#define WNBR    32
#define M_TOT   (BATCH * S_LEN)      // 8192

// ---------------------------------------------------------------------------
// PTX helpers — base sm_103 only (NO tcgen05)
// ---------------------------------------------------------------------------
__device__ __forceinline__ uint32_t smem_to_u32(const void* p) {
    uint32_t a;
    asm("{ .reg .u64 t; cvta.to.shared.u64 t, %1; cvt.u32.u64 %0, t; }" : "=r"(a) : "l"(p));
    return a;
}
__device__ __forceinline__ void ldsm_x4(uint32_t* r, uint32_t addr) {
    asm volatile("ldmatrix.sync.aligned.m8n8.x4.shared.b16 {%0,%1,%2,%3}, [%4];"
                 : "=r"(r[0]), "=r"(r[1]), "=r"(r[2]), "=r"(r[3]) : "r"(addr));
}
__device__ __forceinline__ void mma_f16_16816(float* d, const uint32_t* a,
                                              uint32_t b0, uint32_t b1) {
    asm volatile(
        "mma.sync.aligned.m16n8k16.row.col.f32.f16.f16.f32 "
        "{%0,%1,%2,%3}, {%4,%5,%6,%7}, {%8,%9}, {%0,%1,%2,%3};"
        : "+f"(d[0]), "+f"(d[1]), "+f"(d[2]), "+f"(d[3])
        : "r"(a[0]), "r"(a[1]), "r"(a[2]), "r"(a[3]), "r"(b0), "r"(b1));
}
#define CP_ASYNC16(sa, gp) \
    asm volatile("cp.async.cg.shared.global [%0], [%1], 16;" :: "r"(sa), "l"(gp))
#define CP_COMMIT() asm volatile("cp.async.commit_group;")
#define CP_WAIT1()  asm volatile("cp.async.wait_group 1;")
#define CP_WAIT0()  asm volatile("cp.async.wait_group 0;")

// ---------------------------------------------------------------------------
// Scratch (allocation-free rule: device globals)
// ---------------------------------------------------------------------------
__device__ __align__(256) __half g_q16[M_TOT * DMODEL];   // Q fp16
__device__ __align__(256) __half g_k16[M_TOT * DMODEL];   // K fp16
__device__ __align__(256) __half g_v16[M_TOT * DMODEL];   // V fp16
__device__ __align__(256) __half g_x16[M_TOT * DMODEL];   // x fp16 (later attn-out)
// weights fp16: rows 0..511 Wq, 512..1023 Wk, 1024..1535 Wv, 1536..2047 Wo
__device__ __align__(256) __half g_w16[4 * DMODEL * DMODEL];

// ---------------------------------------------------------------------------
// Fused prep: convert x and the 4 weight matrices to fp16
// ---------------------------------------------------------------------------
#define NX4  (M_TOT * DMODEL / 4)            // 1048576
#define NW4  (DMODEL * DMODEL / 4)           // 65536

__global__ __launch_bounds__(256)
void prep_kernel(const float* __restrict__ x,
                 const float* __restrict__ w0, const float* __restrict__ w1,
                 const float* __restrict__ w2, const float* __restrict__ w3,
                 __half* __restrict__ x16, __half* __restrict__ w16)
{
    int i = blockIdx.x * blockDim.x + threadIdx.x;
    const float* src;
    __half* dst;
    int l;
    if (i < NX4) {
        src = x; dst = x16; l = i;
    } else {
        int j = i - NX4;
        int w = j >> 16;  l = j & (NW4 - 1);
        src = (w == 0) ? w0 : (w == 1) ? w1 : (w == 2) ? w2 : w3;
        dst = w16 + (size_t)w * DMODEL * DMODEL;
    }
    float4 v = ((const float4*)src)[l];
    ((__half2*)dst)[l * 2 + 0] = __floats2half2_rn(v.x, v.y);
    ((__half2*)dst)[l * 2 + 1] = __floats2half2_rn(v.z, v.w);
}

// ---------------------------------------------------------------------------
// Pure fp16 HMMA GEMM: C = A * B^T (row-major, K-major), fp32 accum.
// CTA 128x128, BK=32, 256 threads, warp grid 2(M) x 4(N), warp tile 64x32.
// 3-stage cp.async pipeline, ONE __syncthreads per K-chunk.
// EPI: 0 = fp32 C ; 1 = QKV fp16 (q / k / v selected by n0 block)
// ---------------------------------------------------------------------------
#define ASTRIDE 40
#define TILE_B  (128 * ASTRIDE * 2)   // 10240 B per 128x32 tile
#define BUF_B   (2 * TILE_B)          // A|B = 20480
#define NSTAGE  3
#define GEMM_SMEM (NSTAGE * BUF_B)    // 61440

template <int EPI>
__device__ __forceinline__
void gemm_core(const __half* __restrict__ A, const __half* __restrict__ B,
               float* __restrict__ C, __half* __restrict__ Q16,
               __half* __restrict__ K16, __half* __restrict__ V16)
{
    extern __shared__ char smc[];
    const uint32_t sbase = smem_to_u32(smc);
    const int t = threadIdx.x, lane = t & 31, wid = t >> 5;
    const int wm = wid & 1, wn = wid >> 1;
    const int m0 = blockIdx.y * 128;
    const int n0 = blockIdx.x * 128;

    float acc[4][4][4];
#pragma unroll
    for (int mi = 0; mi < 4; mi++)
#pragma unroll
        for (int ni = 0; ni < 4; ni++)
#pragma unroll
            for (int j = 0; j < 4; j++) acc[mi][ni][j] = 0.0f;

    const int e0row = t >> 2,         e0c = (t & 3) * 8;
    const int e1row = (t + 256) >> 2, e1c = ((t + 256) & 3) * 8;
    const uint32_t so0 = (uint32_t)(e0row * ASTRIDE + e0c) * 2;
    const uint32_t so1 = (uint32_t)(e1row * ASTRIDE + e1c) * 2;

#define LOAD_CHUNK(kc, buf) do { \
    uint32_t bb = sbase + (uint32_t)(buf) * BUF_B; \
    size_t ga0 = (size_t)(m0 + e0row) * DMODEL + (kc) + e0c; \
    size_t ga1 = (size_t)(m0 + e1row) * DMODEL + (kc) + e1c; \
    size_t gb0 = (size_t)(n0 + e0row) * DMODEL + (kc) + e0c; \
    size_t gb1 = (size_t)(n0 + e1row) * DMODEL + (kc) + e1c; \
    CP_ASYNC16(bb + so0,          A + ga0); \
    CP_ASYNC16(bb + so1,          A + ga1); \
    CP_ASYNC16(bb + TILE_B + so0, B + gb0); \
    CP_ASYNC16(bb + TILE_B + so1, B + gb1); \
} while (0)

    // Prologue: 2 chunks in flight
    LOAD_CHUNK(0, 0);
    CP_COMMIT();
    LOAD_CHUNK(32, 1);
    CP_COMMIT();

    const int lrow = lane & 15;
    const int lcol = lane >> 4;

    for (int c = 0; c < 16; c++) {
        CP_WAIT1();                    // chunk c resident
        __syncthreads();               // all copies visible; buf (c+2)%3 free
        if (c < 14) LOAD_CHUNK((c + 2) * 32, (c + 2) % NSTAGE);
        CP_COMMIT();

        const uint32_t ab = sbase + (uint32_t)(c % NSTAGE) * BUF_B;
#pragma unroll
        for (int ks = 0; ks < 2; ks++) {
            uint32_t af[4][4], bf[2][4];
            const int kcol = ks * 2 + lcol;
#pragma unroll
            for (int mi = 0; mi < 4; mi++) {
                uint32_t ad = ab + (uint32_t)(((wm * 64 + mi * 16 + lrow) * ASTRIDE) + kcol * 8) * 2;
                ldsm_x4(af[mi], ad);
            }
#pragma unroll
            for (int nb = 0; nb < 2; nb++) {
                uint32_t bd = ab + TILE_B +
                              (uint32_t)(((wn * 32 + nb * 16 + lrow) * ASTRIDE) + kcol * 8) * 2;
                ldsm_x4(bf[nb], bd);
            }
#pragma unroll
            for (int mi = 0; mi < 4; mi++)
#pragma unroll
                for (int ni = 0; ni < 4; ni++) {
                    const int nb = ni >> 1, nl = ni & 1;
                    mma_f16_16816(acc[mi][ni], af[mi], bf[nb][nl], bf[nb][nl + 2]);
                }
        }
    }
#undef LOAD_CHUNK

    if (EPI == 0) {
#pragma unroll
        for (int mi = 0; mi < 4; mi++) {
            const int r0 = m0 + wm * 64 + mi * 16 + (lane >> 2);
#pragma unroll
            for (int ni = 0; ni < 4; ni++) {
                const int cc = n0 + wn * 32 + ni * 8 + (lane & 3) * 2;
                *(float2*)(C + (size_t)r0 * DMODEL + cc)       = make_float2(acc[mi][ni][0], acc[mi][ni][1]);
                *(float2*)(C + (size_t)(r0 + 8) * DMODEL + cc) = make_float2(acc[mi][ni][2], acc[mi][ni][3]);
            }
        }
    } else {
        __half* dst;
        int nb0;
        if (n0 < 512)       { dst = Q16; nb0 = n0; }
        else if (n0 < 1024) { dst = K16; nb0 = n0 - 512; }
        else                { dst = V16; nb0 = n0 - 1024; }
#pragma unroll
        for (int mi = 0; mi < 4; mi++) {
            const int r0 = m0 + wm * 64 + mi * 16 + (lane >> 2);
#pragma unroll
            for (int ni = 0; ni < 4; ni++) {
                const int cc = nb0 + wn * 32 + ni * 8 + (lane & 3) * 2;
                *(__half2*)(dst + (size_t)r0 * DMODEL + cc) =
                    __floats2half2_rn(acc[mi][ni][0], acc[mi][ni][1]);
                *(__half2*)(dst + (size_t)(r0 + 8) * DMODEL + cc) =
                    __floats2half2_rn(acc[mi][ni][2], acc[mi][ni][3]);
            }
        }
    }
}

__global__ __launch_bounds__(256, 2)
void gemm_qkv(const __half* __restrict__ A, const __half* __restrict__ B,
              __half* __restrict__ Q16, __half* __restrict__ K16, __half* __restrict__ V16)
{
    gemm_core<1>(A, B, nullptr, Q16, K16, V16);
}

__global__ __launch_bounds__(256, 2)
void gemm_out(const __half* __restrict__ A, const __half* __restrict__ B,
              float* __restrict__ C)
{
    gemm_core<0>(A, B, C, nullptr, nullptr, nullptr);
}

// ---------------------------------------------------------------------------
// Neighbor attention: K staged via cp.async (33 KB smem), V gathered directly
// from L2 per-warp (first 16 rows prefetched before softmax). One CTA per
// (b,s); 8 warps = 8 heads. q fp16 in, output fp16.
// ---------------------------------------------------------------------------
#define PITCH_H 520                          // halves; row stride 1040 B
#define ATT_SMEM (WNBR * PITCH_H * 2)        // 33280 B

__global__ __launch_bounds__(256, 6)
void attn_kernel(const __half* __restrict__ q16,
                 const __half* __restrict__ k16,
                 const __half* __restrict__ v16,
                 const int*   __restrict__ nidx,
                 __half* __restrict__ a16)
{
    extern __shared__ char smc[];
    const uint32_t sbase = smem_to_u32(smc);
    __shared__ int   sj[WNBR];
    __shared__ float sq[DMODEL];

    const int bs   = blockIdx.x;
    const int s    = bs & (S_LEN - 1);
    const int b    = bs >> 12;
    const int t    = threadIdx.x;
    const int h    = t >> 5;
    const int lane = t & 31;

    if (t < WNBR) sj[t] = nidx[s * WNBR + t];
    {
        __half2 qh = *(const __half2*)(q16 + (size_t)bs * DMODEL + t * 2);
        float2 qf = __half22float2(qh);
        sq[t * 2]     = qf.x;
        sq[t * 2 + 1] = qf.y;
    }
    __syncthreads();

    // Stage K rows: 32 rows x 1024 B, 64 16B-chunks per row, 8 per thread.
#pragma unroll
    for (int i = 0; i < 8; i++) {
        int e = t + i * 256;
        int w = e >> 6, c = e & 63;
        size_t src = (size_t)(b * S_LEN + sj[w]) * DMODEL + c * 8;
        CP_ASYNC16(sbase + (uint32_t)(w * 1040 + c * 16), k16 + src);
    }
    CP_COMMIT();
    CP_WAIT0();
    __syncthreads();

    // Scores: lane owns neighbor `lane`
    float acc = 0.0f;
    {
        const char* kr = smc + lane * 1040 + h * 128;
        const float* qr = sq + h * DHEAD;
#pragma unroll
        for (int i = 0; i < 8; i++) {
            uint4 kv = *(const uint4*)(kr + i * 16);
            float4 q0 = *(const float4*)(qr + i * 8);
            float4 q1 = *(const float4*)(qr + i * 8 + 4);
            float2 f0 = __half22float2(*(__half2*)&kv.x);
            float2 f1 = __half22float2(*(__half2*)&kv.y);
            float2 f2 = __half22float2(*(__half2*)&kv.z);
            float2 f3 = __half22float2(*(__half2*)&kv.w);
            acc += q0.x * f0.x + q0.y * f0.y + q0.z * f1.x + q0.w * f1.y
                 + q1.x * f2.x + q1.y * f2.y + q1.z * f3.x + q1.w * f3.y;
        }
    }
    float score = acc * 0.125f;

    // Prefetch V rows 0..15 (depend only on sj) before the softmax chain
    const __half* vbase = v16 + (size_t)b * S_LEN * DMODEL + h * DHEAD + lane * 2;
    float2 vpre[16];
#pragma unroll
    for (int u = 0; u < 16; u++)
        vpre[u] = __half22float2(*(const __half2*)(vbase + (size_t)sj[u] * DMODEL));

    // Warp softmax
    float m = score;
#pragma unroll
    for (int o = 16; o; o >>= 1) m = fmaxf(m, __shfl_xor_sync(0xffffffffu, m, o));
    float e = expf(score - m);
    float ssum = e;
#pragma unroll
    for (int o = 16; o; o >>= 1) ssum += __shfl_xor_sync(0xffffffffu, ssum, o);
    float p = e / ssum;

    // PV: prefetched rows, then the remaining two 8-deep batches
    float ox = 0.0f, oy = 0.0f;
#pragma unroll
    for (int u = 0; u < 16; u++) {
        float pw = __shfl_sync(0xffffffffu, p, u);
        ox += pw * vpre[u].x;
        oy += pw * vpre[u].y;
    }
#pragma unroll
    for (int w0 = 16; w0 < WNBR; w0 += 8) {
        float2 vv[8];
#pragma unroll
        for (int u = 0; u < 8; u++)
            vv[u] = __half22float2(*(const __half2*)(vbase + (size_t)sj[w0 + u] * DMODEL));
#pragma unroll
        for (int u = 0; u < 8; u++) {
            float pw = __shfl_sync(0xffffffffu, p, w0 + u);
            ox += pw * vv[u].x;
            oy += pw * vv[u].y;
        }
    }

    // fp16 output (feeds final GEMM directly)
    const size_t oidx = (size_t)bs * DMODEL + h * DHEAD + lane * 2;
    *(__half2*)(a16 + oidx) = __floats2half2_rn(ox, oy);
}

// ---------------------------------------------------------------------------
extern "C" void kernel_launch(void* const* d_in, const int* in_sizes, int n_in,
                              void* d_out, int out_size)
{
    const float* x    = (const float*)d_in[0];
    const float* Wq   = (const float*)d_in[1];
    const float* Wk   = (const float*)d_in[2];
    const float* Wv   = (const float*)d_in[3];
    const float* Wo   = (const float*)d_in[4];
    const int*   nidx = (const int*)  d_in[5];
    float*       out  = (float*)d_out;

    __half *q16, *k16, *v16, *x16, *w16;
    cudaGetSymbolAddress((void**)&q16, g_q16);
    cudaGetSymbolAddress((void**)&k16, g_k16);
    cudaGetSymbolAddress((void**)&v16, g_v16);
    cudaGetSymbolAddress((void**)&x16, g_x16);
    cudaGetSymbolAddress((void**)&w16, g_w16);

    static int attr_set = 0;
    if (!attr_set) {
        cudaFuncSetAttribute(attn_kernel, cudaFuncAttributeMaxDynamicSharedMemorySize, ATT_SMEM);
        cudaFuncSetAttribute(gemm_qkv,    cudaFuncAttributeMaxDynamicSharedMemorySize, GEMM_SMEM);
        cudaFuncSetAttribute(gemm_out,    cudaFuncAttributeMaxDynamicSharedMemorySize, GEMM_SMEM);
        attr_set = 1;
    }

    const int NW = DMODEL * DMODEL;           // 262144

    prep_kernel<<<(NX4 + 4 * NW4) / 256, 256>>>(x, Wq, Wk, Wv, Wo, x16, w16);

    dim3 qkvgrid(3 * DMODEL / 128, M_TOT / 128);   // (12, 64)
    gemm_qkv<<<qkvgrid, 256, GEMM_SMEM>>>(x16, w16, q16, k16, v16);

    attn_kernel<<<M_TOT, 256, ATT_SMEM>>>(q16, k16, v16, nidx, x16);

    dim3 ogrid(DMODEL / 128, M_TOT / 128);         // (4, 64)
    gemm_out<<<ogrid, 256, GEMM_SMEM>>>(x16, w16 + 3 * NW, out);
}